// round 1
// baseline (speedup 1.0000x reference)
#include <cuda_runtime.h>
#include <cuda_bf16.h>
#include <cstdint>

#define VOCAB 30000
#define TT    512
#define BATCH 4096
#define HH    100
#define NG    400      // 4 gates * 100
#define EE    32
#define BB    32       // batch per CTA
#define NBLK  128      // BATCH / BB
#define NTH   416      // 13 warps; 400 active compute threads
#define ACT   400
#define HPAD  104      // padded h row (floats)

// 48 MB precomputed table: xpre[v][n] = bias_g[j] + emb[v]·Wg[0:32, j], n = g*100+j
__device__ float g_xpre[(size_t)VOCAB * NG];

__device__ __forceinline__ float fsigm(float z) {
    return __fdividef(1.f, 1.f + __expf(-z));
}
__device__ __forceinline__ float ftanh(float z) {
    return 1.f - __fdividef(2.f, __expf(2.f * z) + 1.f);
}

// ---------------------------------------------------------------------------
// Kernel 1: build the per-vocab gate-preactivation table (x-part + bias)
// ---------------------------------------------------------------------------
__global__ void xpre_kernel(const float* __restrict__ emb,
                            const float* __restrict__ Wf, const float* __restrict__ bf,
                            const float* __restrict__ Wi, const float* __restrict__ bi,
                            const float* __restrict__ Wo, const float* __restrict__ bo,
                            const float* __restrict__ Wc, const float* __restrict__ bc) {
    int v = blockIdx.x;
    __shared__ float e[EE];
    if (threadIdx.x < EE) e[threadIdx.x] = emb[v * EE + threadIdx.x];
    __syncthreads();
    for (int n = threadIdx.x; n < NG; n += blockDim.x) {
        int g = n / HH, j = n % HH;
        const float* W = (g == 0) ? Wf : (g == 1) ? Wi : (g == 2) ? Wo : Wc;
        const float* b = (g == 0) ? bf : (g == 1) ? bi : (g == 2) ? bo : bc;
        float s = b[j];
#pragma unroll
        for (int k = 0; k < EE; k++) s = fmaf(e[k], W[k * HH + j], s);
        g_xpre[(size_t)v * NG + n] = s;
    }
}

// ---------------------------------------------------------------------------
// Kernel 2: persistent LSTM. One CTA owns 32 batch elements for all 511 steps.
// SMEM: Wh (100x400 fp32, h-part of all 4 gate weights), gates buffer, h state.
// ---------------------------------------------------------------------------
__global__ void __launch_bounds__(NTH, 1)
lstm_kernel(const int* __restrict__ data32,
            const float* __restrict__ Wf, const float* __restrict__ Wi,
            const float* __restrict__ Wo4, const float* __restrict__ Wc,
            const float* __restrict__ WoOut, const float* __restrict__ boOut,
            float* __restrict__ out) {
    extern __shared__ float smem[];
    float* Whs = smem;                    // [100][400]
    float* gs  = smem + 40000;            // [32][400]  activated gates
    float* hs  = smem + 52800;            // [32][104]  h state
    int*   itk = (int*)(smem + 52800 + BB * HPAD);
    int*   toks = itk;                    // [2][32] double-buffered tokens
    int*   ltok = itk + 2 * BB;           // [32] last token per b
    int*   flag = itk + 3 * BB;           // [0] = is64

    const int tid = threadIdx.x;
    const int b0  = blockIdx.x * BB;

    // detect int64 vs int32 token storage (tokens < 30000 => high words all 0)
    if (tid == 0) {
        int is64 = 1;
        for (int i = 0; i < 64; i++)
            if (data32[2 * i + 1] != 0) { is64 = 0; break; }
        flag[0] = is64;
    }
    // stage Wh (rows 32..131 of each gate weight) into SMEM, layout [k][n]
    for (int idx = tid; idx < HH * NG; idx += NTH) {
        int k = idx / NG, n = idx % NG, g = n / HH, j = n % HH;
        const float* W = (g == 0) ? Wf : (g == 1) ? Wi : (g == 2) ? Wo4 : Wc;
        Whs[idx] = W[(EE + k) * HH + j];
    }
    for (int idx = tid; idx < BB * HPAD; idx += NTH) hs[idx] = 0.f;
    __syncthreads();

    const int is64 = flag[0];
    if (tid < BB) {
        long long base = (long long)(b0 + tid) * TT;
        ltok[tid]       = is64 ? data32[2 * (base + TT - 1)] : data32[base + TT - 1];
        toks[tid]       = is64 ? data32[2 * base]            : data32[base];
    }
    __syncthreads();

    const bool active = (tid < ACT);
    const int  bg = tid / 100;   // batch group (0..3), 8 b each
    const int  ng = tid % 100;   // n group, 4 consecutive n

    float c[8];
#pragma unroll
    for (int i = 0; i < 8; i++) c[i] = 0.f;

    int cur = 0;
    for (int t = 0; t < TT - 1; ++t) {
        // prefetch next step's tokens into the other buffer
        if (tid < BB) {
            long long base = (long long)(b0 + tid) * TT + (t + 1);
            toks[(cur ^ 1) * BB + tid] = is64 ? data32[2 * base] : data32[base];
        }

        if (active) {
            // issue xpre gathers early (consumed after K-loop)
            float4 xp[8];
            float  acc[8][4];
#pragma unroll
            for (int i = 0; i < 8; i++) {
                int tk = toks[cur * BB + bg * 8 + i];
                xp[i] = __ldg((const float4*)(g_xpre + (size_t)tk * NG + ng * 4));
                acc[i][0] = 0.f; acc[i][1] = 0.f; acc[i][2] = 0.f; acc[i][3] = 0.f;
            }
            const float4* Wr = (const float4*)Whs;
#pragma unroll 1
            for (int k = 0; k < HH; k += 4) {
                float4 h4[8];
#pragma unroll
                for (int i = 0; i < 8; i++)
                    h4[i] = *(const float4*)(hs + (bg * 8 + i) * HPAD + k);
#pragma unroll
                for (int kk = 0; kk < 4; kk++) {
                    float4 w = Wr[(k + kk) * 100 + ng];
#pragma unroll
                    for (int i = 0; i < 8; i++) {
                        float hv = (kk == 0) ? h4[i].x : (kk == 1) ? h4[i].y
                                 : (kk == 2) ? h4[i].z : h4[i].w;
                        acc[i][0] = fmaf(hv, w.x, acc[i][0]);
                        acc[i][1] = fmaf(hv, w.y, acc[i][1]);
                        acc[i][2] = fmaf(hv, w.z, acc[i][2]);
                        acc[i][3] = fmaf(hv, w.w, acc[i][3]);
                    }
                }
            }
            // add x-part, activate (ng<75: sigmoid gates f,i,o ; ng>=75: tanh g)
            const bool isg = (ng >= 75);
#pragma unroll
            for (int i = 0; i < 8; i++) {
                float z0 = acc[i][0] + xp[i].x, z1 = acc[i][1] + xp[i].y;
                float z2 = acc[i][2] + xp[i].z, z3 = acc[i][3] + xp[i].w;
                float4 a;
                if (isg) { a.x = ftanh(z0); a.y = ftanh(z1); a.z = ftanh(z2); a.w = ftanh(z3); }
                else     { a.x = fsigm(z0); a.y = fsigm(z1); a.z = fsigm(z2); a.w = fsigm(z3); }
                *(float4*)(gs + (bg * 8 + i) * NG + ng * 4) = a;
            }
        }
        __syncthreads();

        // phase 2: combine gates -> c (regs), h (SMEM); masked update
        if (active) {
#pragma unroll
            for (int i = 0; i < 8; i++) {
                int p = tid + ACT * i;        // 0..3199
                int b = p / HH, j = p % HH;
                if (toks[cur * BB + b] != ltok[b]) {
                    float f  = gs[b * NG + j];
                    float ii = gs[b * NG + 100 + j];
                    float o  = gs[b * NG + 200 + j];
                    float g  = gs[b * NG + 300 + j];
                    float cn = fmaf(c[i], f, ii * g);
                    c[i] = cn;
                    hs[b * HPAD + j] = o * ftanh(cn);
                }
            }
        }
        cur ^= 1;
        __syncthreads();
    }

    // output head: out[b] = sigmoid(h·Wo + bo)
    if (tid < BB) {
        float z = boOut[0];
#pragma unroll 4
        for (int j = 0; j < HH; j++) z = fmaf(hs[tid * HPAD + j], WoOut[j], z);
        out[b0 + tid] = fsigm(z);
    }
}

// ---------------------------------------------------------------------------
extern "C" void kernel_launch(void* const* d_in, const int* in_sizes, int n_in,
                              void* d_out, int out_size) {
    const int*   data = (const int*)  d_in[0];   // int64 or int32 tokens (auto-detected)
    const float* emb  = (const float*)d_in[1];
    const float* Wfh  = (const float*)d_in[2];
    const float* bfh  = (const float*)d_in[3];
    const float* Wih  = (const float*)d_in[4];
    const float* bih  = (const float*)d_in[5];
    const float* Woh  = (const float*)d_in[6];
    const float* boh  = (const float*)d_in[7];
    const float* Wch  = (const float*)d_in[8];
    const float* bch  = (const float*)d_in[9];
    const float* Wo   = (const float*)d_in[10];
    const float* bo   = (const float*)d_in[11];
    float* out = (float*)d_out;

    xpre_kernel<<<VOCAB, 128>>>(emb, Wfh, bfh, Wih, bih, Woh, boh, Wch, bch);

    const size_t smem_bytes = (size_t)(40000 + 12800 + BB * HPAD) * 4 + 100 * 4;
    cudaFuncSetAttribute(lstm_kernel, cudaFuncAttributeMaxDynamicSharedMemorySize,
                         (int)smem_bytes);
    lstm_kernel<<<NBLK, NTH, smem_bytes>>>(data, Wfh, Wih, Woh, Wch, Wo, bo, out);
}

// round 2
// speedup vs baseline: 1.0688x; 1.0688x over previous
#include <cuda_runtime.h>
#include <cuda_bf16.h>
#include <cstdint>

#define VOCAB 30000
#define TT    512
#define BATCH 4096
#define HH    100
#define NG    400      // 4 gates * 100
#define EE    32
#define BB    32       // batch per CTA
#define NBLK  128      // BATCH / BB
#define NTH   416      // 13 warps; 400 active compute threads
#define ACT   400
#define HPAD  104      // padded h row (floats)

// 48 MB precomputed table: xpre[v][n] = bias_g[j] + emb[v]·Wg[0:32, j], n = g*100+j
__device__ float g_xpre[(size_t)VOCAB * NG];

typedef unsigned long long u64;

__device__ __forceinline__ float fsigm(float z) {
    return __fdividef(1.f, 1.f + __expf(-z));
}
__device__ __forceinline__ float ftanh(float z) {
    return 1.f - __fdividef(2.f, __expf(2.f * z) + 1.f);
}

// ---- packed f32x2 helpers (Blackwell) ----
__device__ __forceinline__ void ffma2(u64& d, u64 a, u64 b) {
    asm("fma.rn.f32x2 %0, %1, %2, %0;" : "+l"(d) : "l"(a), "l"(b));
}
__device__ __forceinline__ u64 fadd2(u64 a, u64 b) {
    u64 r; asm("add.rn.f32x2 %0, %1, %2;" : "=l"(r) : "l"(a), "l"(b)); return r;
}
__device__ __forceinline__ u64 pack2(float v) {
    u64 r; asm("mov.b64 %0, {%1, %1};" : "=l"(r) : "f"(v)); return r;
}
__device__ __forceinline__ float2 unpack2(u64 v) {
    float2 f; asm("mov.b64 {%0, %1}, %2;" : "=f"(f.x), "=f"(f.y) : "l"(v)); return f;
}

// ---------------------------------------------------------------------------
// Kernel 1: build the per-vocab gate-preactivation table (x-part + bias)
// ---------------------------------------------------------------------------
__global__ void xpre_kernel(const float* __restrict__ emb,
                            const float* __restrict__ Wf, const float* __restrict__ bf,
                            const float* __restrict__ Wi, const float* __restrict__ bi,
                            const float* __restrict__ Wo, const float* __restrict__ bo,
                            const float* __restrict__ Wc, const float* __restrict__ bc) {
    int v = blockIdx.x;
    __shared__ float e[EE];
    if (threadIdx.x < EE) e[threadIdx.x] = emb[v * EE + threadIdx.x];
    __syncthreads();
    for (int n = threadIdx.x; n < NG; n += blockDim.x) {
        int g = n / HH, j = n % HH;
        const float* W = (g == 0) ? Wf : (g == 1) ? Wi : (g == 2) ? Wo : Wc;
        const float* b = (g == 0) ? bf : (g == 1) ? bi : (g == 2) ? bo : bc;
        float s = b[j];
#pragma unroll
        for (int k = 0; k < EE; k++) s = fmaf(e[k], W[k * HH + j], s);
        g_xpre[(size_t)v * NG + n] = s;
    }
}

// ---------------------------------------------------------------------------
// Kernel 2: persistent LSTM with packed f32x2 recurrent GEMM.
// ---------------------------------------------------------------------------
__global__ void __launch_bounds__(NTH, 1)
lstm_kernel(const int* __restrict__ data32,
            const float* __restrict__ Wf, const float* __restrict__ Wi,
            const float* __restrict__ Wo4, const float* __restrict__ Wc,
            const float* __restrict__ WoOut, const float* __restrict__ boOut,
            float* __restrict__ out) {
    extern __shared__ float smem[];
    float* Whs = smem;                    // [100][400]
    float* gs  = smem + 40000;            // [32][400]  activated gates
    float* hs  = smem + 52800;            // [32][104]  h state
    int*   itk = (int*)(smem + 52800 + BB * HPAD);
    int*   toks = itk;                    // [2][32] double-buffered tokens
    int*   ltok = itk + 2 * BB;           // [32] last token per b
    int*   flag = itk + 3 * BB;           // [0] = is64

    const int tid = threadIdx.x;
    const int b0  = blockIdx.x * BB;

    // detect int64 vs int32 token storage (tokens < 30000 => high words all 0)
    if (tid == 0) {
        int is64 = 1;
        for (int i = 0; i < 64; i++)
            if (data32[2 * i + 1] != 0) { is64 = 0; break; }
        flag[0] = is64;
    }
    // stage Wh (rows 32..131 of each gate weight) into SMEM, layout [k][n]
    for (int idx = tid; idx < HH * NG; idx += NTH) {
        int k = idx / NG, n = idx % NG, g = n / HH, j = n % HH;
        const float* W = (g == 0) ? Wf : (g == 1) ? Wi : (g == 2) ? Wo4 : Wc;
        Whs[idx] = W[(EE + k) * HH + j];
    }
    for (int idx = tid; idx < BB * HPAD; idx += NTH) hs[idx] = 0.f;
    __syncthreads();

    const int is64 = flag[0];
    if (tid < BB) {
        long long base = (long long)(b0 + tid) * TT;
        ltok[tid] = is64 ? data32[2 * (base + TT - 1)] : data32[base + TT - 1];
        toks[tid] = is64 ? data32[2 * base]            : data32[base];
    }
    __syncthreads();

    const bool active = (tid < ACT);
    const int  bg = tid / 100;   // batch group (0..3), 8 b each
    const int  ng = tid % 100;   // n group: 4 consecutive gate outputs (2 f32x2 pairs)

    float c[8];
#pragma unroll
    for (int i = 0; i < 8; i++) c[i] = 0.f;

    int cur = 0;
    for (int t = 0; t < TT - 1; ++t) {
        // prefetch next step's tokens into the other buffer
        if (tid < BB) {
            long long base = (long long)(b0 + tid) * TT + (t + 1);
            toks[(cur ^ 1) * BB + tid] = is64 ? data32[2 * base] : data32[base];
        }

        if (active) {
            // issue xpre gathers early (consumed in epilogue, after K loop)
            ulonglong2 xp[8];
            u64 acc[8][2];
#pragma unroll
            for (int i = 0; i < 8; i++) {
                int tk = toks[cur * BB + bg * 8 + i];
                xp[i] = __ldg((const ulonglong2*)(g_xpre + (size_t)tk * NG + ng * 4));
                acc[i][0] = 0ull; acc[i][1] = 0ull;
            }
            const ulonglong2* Wr2 = (const ulonglong2*)Whs;
#pragma unroll 1
            for (int k = 0; k < HH; k += 4) {
                float4 h4[8];
#pragma unroll
                for (int i = 0; i < 8; i++)
                    h4[i] = *(const float4*)(hs + (bg * 8 + i) * HPAD + k);
#pragma unroll
                for (int kk = 0; kk < 4; kk++) {
                    ulonglong2 w2 = Wr2[(k + kk) * 100 + ng];
#pragma unroll
                    for (int i = 0; i < 8; i++) {
                        float hv = (kk == 0) ? h4[i].x : (kk == 1) ? h4[i].y
                                 : (kk == 2) ? h4[i].z : h4[i].w;
                        u64 hp = pack2(hv);
                        ffma2(acc[i][0], hp, w2.x);
                        ffma2(acc[i][1], hp, w2.y);
                    }
                }
            }
            // add x-part, activate (ng<75: sigmoid gates f,i,o ; ng>=75: tanh g)
            const bool isg = (ng >= 75);
#pragma unroll
            for (int i = 0; i < 8; i++) {
                float2 z01 = unpack2(fadd2(acc[i][0], xp[i].x));
                float2 z23 = unpack2(fadd2(acc[i][1], xp[i].y));
                float4 a;
                if (isg) { a.x = ftanh(z01.x); a.y = ftanh(z01.y);
                           a.z = ftanh(z23.x); a.w = ftanh(z23.y); }
                else     { a.x = fsigm(z01.x); a.y = fsigm(z01.y);
                           a.z = fsigm(z23.x); a.w = fsigm(z23.y); }
                *(float4*)(gs + (bg * 8 + i) * NG + ng * 4) = a;
            }
        }
        __syncthreads();

        // phase 2: combine gates -> c (regs), h (SMEM); masked update
        if (active) {
#pragma unroll
            for (int i = 0; i < 8; i++) {
                int p = tid + ACT * i;        // 0..3199
                int b = p / HH, j = p % HH;
                if (toks[cur * BB + b] != ltok[b]) {
                    float f  = gs[b * NG + j];
                    float ii = gs[b * NG + 100 + j];
                    float o  = gs[b * NG + 200 + j];
                    float g  = gs[b * NG + 300 + j];
                    float cn = fmaf(c[i], f, ii * g);
                    c[i] = cn;
                    hs[b * HPAD + j] = o * ftanh(cn);
                }
            }
        }
        cur ^= 1;
        __syncthreads();
    }

    // output head: out[b] = sigmoid(h·Wo + bo)
    if (tid < BB) {
        float z = boOut[0];
#pragma unroll 4
        for (int j = 0; j < HH; j++) z = fmaf(hs[tid * HPAD + j], WoOut[j], z);
        out[b0 + tid] = fsigm(z);
    }
}

// ---------------------------------------------------------------------------
extern "C" void kernel_launch(void* const* d_in, const int* in_sizes, int n_in,
                              void* d_out, int out_size) {
    const int*   data = (const int*)  d_in[0];   // int64 or int32 tokens (auto-detected)
    const float* emb  = (const float*)d_in[1];
    const float* Wfh  = (const float*)d_in[2];
    const float* bfh  = (const float*)d_in[3];
    const float* Wih  = (const float*)d_in[4];
    const float* bih  = (const float*)d_in[5];
    const float* Woh  = (const float*)d_in[6];
    const float* boh  = (const float*)d_in[7];
    const float* Wch  = (const float*)d_in[8];
    const float* bch  = (const float*)d_in[9];
    const float* Wo   = (const float*)d_in[10];
    const float* bo   = (const float*)d_in[11];
    float* out = (float*)d_out;

    xpre_kernel<<<VOCAB, 128>>>(emb, Wfh, bfh, Wih, bih, Woh, boh, Wch, bch);

    const size_t smem_bytes = (size_t)(40000 + 12800 + BB * HPAD) * 4 + 100 * 4;
    cudaFuncSetAttribute(lstm_kernel, cudaFuncAttributeMaxDynamicSharedMemorySize,
                         (int)smem_bytes);
    lstm_kernel<<<NBLK, NTH, smem_bytes>>>(data, Wfh, Wih, Woh, Wch, Wo, bo, out);
}